// round 4
// baseline (speedup 1.0000x reference)
#include <cuda_runtime.h>
#include <stdint.h>

#define LATENT 64
#define HID    32
#define EDIM   4
#define N_NODES_MAX 100000
#define TILE_E 64

// Scratch (allocation-free rule: static __device__ arrays) — kept to the
// footprint that is known to load on this container (~14.4 MB).
__device__ float g_P1[N_NODES_MAX * HID];    // x @ 0.5*(W1_min + W1_max)
__device__ float g_PD[N_NODES_MAX * EDIM];   // x @ 0.5*(Wd_min + Wd_max)
__device__ int   g_flag;                     // 0 => edge_index is int64, 1 => int32

// ---------- packed f32x2 helpers (sm_100a+: full-rate fp32 via FFMA2) ----------
__device__ __forceinline__ unsigned long long pack_dup(float a) {
    unsigned long long r;
    asm("mov.b64 %0, {%1, %1};" : "=l"(r) : "f"(a));
    return r;
}
__device__ __forceinline__ void ffma2(unsigned long long &acc,
                                      unsigned long long a,
                                      unsigned long long b) {
    asm("fma.rn.f32x2 %0, %1, %2, %0;" : "+l"(acc) : "l"(a), "l"(b));
}
__device__ __forceinline__ float2 unpack2(unsigned long long v) {
    float2 f;
    asm("mov.b64 {%0, %1}, %2;" : "=f"(f.x), "=f"(f.y) : "l"(v));
    return f;
}

// ---------------- dtype detection ----------------
__global__ void reset_flag_kernel() { g_flag = 0; }

// Reads the first n_probe int64 words. That byte range fits the buffer under
// BOTH dtype interpretations (n_edges int64 == 2*n_edges int32). If storage is
// int32, two fused indices virtually always exceed n_nodes -> flag=1.
__global__ __launch_bounds__(256) void probe_kernel(
    const long long* __restrict__ e, int n_probe, int n_nodes)
{
    int i = blockIdx.x * 256 + threadIdx.x;
    if (i >= n_probe) return;
    long long v = __ldg(&e[i]);
    if (v < 0 || v >= (long long)n_nodes) atomicOr(&g_flag, 1);
}

// ---------------- Kernel A: per-node precompute P1 = x@Ws1, PD = x@WsD ----------------
__global__ __launch_bounds__(256) void node_pre_kernel(
    const float* __restrict__ x,
    const float* __restrict__ W1,     // [128,32]
    const float* __restrict__ Wdir,   // [128,4]
    int n_nodes)
{
    __shared__ float sWs1[LATENT][HID];
    __shared__ float sWsD[LATENT][EDIM];
    int t = threadIdx.x;
    for (int i = t; i < LATENT * HID; i += 256) {
        int j = i >> 5, k = i & 31;
        sWs1[j][k] = 0.5f * (W1[j * HID + k] + W1[(j + LATENT) * HID + k]);
    }
    for (int i = t; i < LATENT * EDIM; i += 256) {
        int j = i >> 2, c = i & 3;
        sWsD[j][c] = 0.5f * (Wdir[j * EDIM + c] + Wdir[(j + LATENT) * EDIM + c]);
    }
    __syncthreads();

    int warp = t >> 5, lane = t & 31;
    int node = blockIdx.x * 8 + warp;
    if (node >= n_nodes) return;

    const float4* xr = (const float4*)(x + (size_t)node * LATENT);
    float acc = 0.f, accd = 0.f;
    #pragma unroll
    for (int i = 0; i < 16; i++) {
        float4 v = xr[i];           // same address all lanes -> broadcast LDG
        int j = i * 4;
        acc = fmaf(v.x, sWs1[j    ][lane], acc);
        acc = fmaf(v.y, sWs1[j + 1][lane], acc);
        acc = fmaf(v.z, sWs1[j + 2][lane], acc);
        acc = fmaf(v.w, sWs1[j + 3][lane], acc);
        if (lane < EDIM) {
            accd = fmaf(v.x, sWsD[j    ][lane], accd);
            accd = fmaf(v.y, sWsD[j + 1][lane], accd);
            accd = fmaf(v.z, sWsD[j + 2][lane], accd);
            accd = fmaf(v.w, sWsD[j + 3][lane], accd);
        }
    }
    g_P1[(size_t)node * HID + lane] = acc;
    if (lane < EDIM) g_PD[(size_t)node * EDIM + lane] = accd;
}

// ---------------- Kernel B: per-edge tiles ----------------
// Block = 128 threads, 64 edges/tile.
// Phase A: gather -> sD[j][e] = |xs-xt| (feature-major), bases from P1/PD.
// Phase B: GEMM1 (64x32, f32x2), relu -> sH
// Phase C: GEMM2 (32x32, f32x2) + residual, relu -> sB1 (reuse)
// Phase D: GEMM3 (W3 32x4) + direct diff (WdD 64x4) + biases -> out
__global__ __launch_bounds__(128) void edge_kernel(
    const float* __restrict__ x,
    const void*  __restrict__ eidx,
    const float* __restrict__ Wdir, const float* __restrict__ bdir,
    const float* __restrict__ W1,   const float* __restrict__ b1,
    const float* __restrict__ W2,   const float* __restrict__ b2,
    const float* __restrict__ W3,   const float* __restrict__ b3,
    float* __restrict__ out, int n_edges, int n_nodes)
{
    __shared__ float sD [LATENT][TILE_E];   // 16 KB  |xs-xt|
    __shared__ float sB1[HID   ][TILE_E];   //  8 KB  sum-path base; later H2
    __shared__ float sBd[EDIM  ][TILE_E];   //  1 KB  direct-path base
    __shared__ float sH [HID   ][TILE_E];   //  8 KB  stage-1 activations
    __shared__ float sWd1[LATENT][HID];     //  8 KB
    __shared__ float sW2 [HID][HID];        //  4 KB
    __shared__ float sW3 [HID][EDIM];       //  0.5 KB
    __shared__ float sWdD[LATENT][EDIM];    //  1 KB
    __shared__ float sb1[HID], sb2[HID], sbo[EDIM];

    int t  = threadIdx.x;
    int e0 = blockIdx.x * TILE_E;

    // ---- stage weights into SMEM ----
    for (int i = t; i < LATENT * HID; i += 128) {
        int j = i >> 5, k = i & 31;
        sWd1[j][k] = 0.5f * (W1[(j + LATENT) * HID + k] - W1[j * HID + k]);
    }
    for (int i = t; i < HID * HID; i += 128) ((float*)sW2)[i] = W2[i];
    if (t < HID * EDIM) ((float*)sW3)[t] = W3[t];
    for (int i = t; i < LATENT * EDIM; i += 128) {
        int j = i >> 2, c = i & 3;
        sWdD[j][c] = 0.5f * (Wdir[(j + LATENT) * EDIM + c] - Wdir[j * EDIM + c]);
    }
    if (t < HID) { sb1[t] = b1[t]; sb2[t] = b2[t]; }
    if (t < EDIM) sbo[t] = b3[t] + bdir[t];

    // ---- Phase A: gather (2 threads per edge, split feature halves) ----
    {
        int e  = t & 63;
        int jh = t >> 6;                  // 0 or 1
        int eg = e0 + e;
        if (eg >= n_edges) eg = n_edges - 1;   // clamp; output guarded later

        // dual-dtype index load (uniform branch on g_flag) + defensive clamp
        int src, tgt;
        if (g_flag == 0) {
            long long s = __ldg(&((const long long*)eidx)[eg]);
            long long d = __ldg(&((const long long*)eidx)[(size_t)n_edges + eg]);
            src = (int)s; tgt = (int)d;
        } else {
            src = __ldg(&((const int*)eidx)[eg]);
            tgt = __ldg(&((const int*)eidx)[(size_t)n_edges + eg]);
        }
        src = min(max(src, 0), n_nodes - 1);
        tgt = min(max(tgt, 0), n_nodes - 1);

        const float4* xs = (const float4*)(x + (size_t)src * LATENT) + jh * 8;
        const float4* xt = (const float4*)(x + (size_t)tgt * LATENT) + jh * 8;
        #pragma unroll
        for (int i = 0; i < 8; i++) {
            float4 a = xs[i], b = xt[i];
            int j = jh * 32 + i * 4;
            sD[j    ][e] = fabsf(a.x - b.x);
            sD[j + 1][e] = fabsf(a.y - b.y);
            sD[j + 2][e] = fabsf(a.z - b.z);
            sD[j + 3][e] = fabsf(a.w - b.w);
        }
        const float4* ps = (const float4*)(g_P1 + (size_t)src * HID) + jh * 4;
        const float4* pt = (const float4*)(g_P1 + (size_t)tgt * HID) + jh * 4;
        #pragma unroll
        for (int i = 0; i < 4; i++) {
            float4 a = ps[i], b = pt[i];
            int k = jh * 16 + i * 4;
            sB1[k    ][e] = a.x + b.x;
            sB1[k + 1][e] = a.y + b.y;
            sB1[k + 2][e] = a.z + b.z;
            sB1[k + 3][e] = a.w + b.w;
        }
        if (jh == 0) {
            float4 a = *(const float4*)(g_PD + (size_t)src * EDIM);
            float4 b = *(const float4*)(g_PD + (size_t)tgt * EDIM);
            sBd[0][e] = a.x + b.x;  sBd[1][e] = a.y + b.y;
            sBd[2][e] = a.z + b.z;  sBd[3][e] = a.w + b.w;
        }
    }
    __syncthreads();

    // ---- Phase B: GEMM1  sH = relu(sD^T @ Wd1 + base + b1) ----
    int mg = t >> 3, ng = t & 7;      // 16 edge-groups x 8 output-groups
    int me = mg * 4, nk = ng * 4;     // 4 edges x 4 outputs per thread
    unsigned long long acc[4][2];
    #pragma unroll
    for (int m = 0; m < 4; m++) { acc[m][0] = 0ull; acc[m][1] = 0ull; }

    #pragma unroll 16
    for (int j = 0; j < LATENT; j++) {
        float4 d4 = *(const float4*)&sD[j][me];
        const unsigned long long* wp = (const unsigned long long*)&sWd1[j][nk];
        unsigned long long w01 = wp[0], w23 = wp[1];
        unsigned long long d0 = pack_dup(d4.x), d1 = pack_dup(d4.y);
        unsigned long long d2 = pack_dup(d4.z), d3 = pack_dup(d4.w);
        ffma2(acc[0][0], d0, w01); ffma2(acc[0][1], d0, w23);
        ffma2(acc[1][0], d1, w01); ffma2(acc[1][1], d1, w23);
        ffma2(acc[2][0], d2, w01); ffma2(acc[2][1], d2, w23);
        ffma2(acc[3][0], d3, w01); ffma2(acc[3][1], d3, w23);
    }
    #pragma unroll
    for (int m = 0; m < 4; m++) {
        float2 a0 = unpack2(acc[m][0]);
        float2 a1 = unpack2(acc[m][1]);
        int e = me + m;
        sH[nk    ][e] = fmaxf(a0.x + sB1[nk    ][e] + sb1[nk    ], 0.f);
        sH[nk + 1][e] = fmaxf(a0.y + sB1[nk + 1][e] + sb1[nk + 1], 0.f);
        sH[nk + 2][e] = fmaxf(a1.x + sB1[nk + 2][e] + sb1[nk + 2], 0.f);
        sH[nk + 3][e] = fmaxf(a1.y + sB1[nk + 3][e] + sb1[nk + 3], 0.f);
    }
    __syncthreads();

    // ---- Phase C: GEMM2  H2 = relu(sH^T @ W2 + b2 + sH), write into sB1 ----
    #pragma unroll
    for (int m = 0; m < 4; m++) { acc[m][0] = 0ull; acc[m][1] = 0ull; }
    #pragma unroll 16
    for (int j = 0; j < HID; j++) {
        float4 h4 = *(const float4*)&sH[j][me];
        const unsigned long long* wp = (const unsigned long long*)&sW2[j][nk];
        unsigned long long w01 = wp[0], w23 = wp[1];
        unsigned long long h0 = pack_dup(h4.x), h1 = pack_dup(h4.y);
        unsigned long long h2 = pack_dup(h4.z), h3 = pack_dup(h4.w);
        ffma2(acc[0][0], h0, w01); ffma2(acc[0][1], h0, w23);
        ffma2(acc[1][0], h1, w01); ffma2(acc[1][1], h1, w23);
        ffma2(acc[2][0], h2, w01); ffma2(acc[2][1], h2, w23);
        ffma2(acc[3][0], h3, w01); ffma2(acc[3][1], h3, w23);
    }
    #pragma unroll
    for (int m = 0; m < 4; m++) {
        float2 a0 = unpack2(acc[m][0]);
        float2 a1 = unpack2(acc[m][1]);
        int e = me + m;
        sB1[nk    ][e] = fmaxf(a0.x + sH[nk    ][e] + sb2[nk    ], 0.f);
        sB1[nk + 1][e] = fmaxf(a0.y + sH[nk + 1][e] + sb2[nk + 1], 0.f);
        sB1[nk + 2][e] = fmaxf(a1.x + sH[nk + 2][e] + sb2[nk + 2], 0.f);
        sB1[nk + 3][e] = fmaxf(a1.y + sH[nk + 3][e] + sb2[nk + 3], 0.f);
    }
    __syncthreads();

    // ---- Phase D: out = H2@W3 + |d|@WdD + (b3 + bdir) + Bd ----
    {
        int e  = t >> 1;
        int c0 = (t & 1) * 2;
        unsigned long long a3 = 0ull;
        #pragma unroll 8
        for (int j = 0; j < HID; j++) {
            unsigned long long hd = pack_dup(sB1[j][e]);
            unsigned long long w  = *(const unsigned long long*)&sW3[j][c0];
            ffma2(a3, hd, w);
        }
        #pragma unroll 8
        for (int j = 0; j < LATENT; j++) {
            unsigned long long dd = pack_dup(sD[j][e]);
            unsigned long long w  = *(const unsigned long long*)&sWdD[j][c0];
            ffma2(a3, dd, w);
        }
        float2 r = unpack2(a3);
        int eg = e0 + e;
        if (eg < n_edges) {
            float2 o;
            o.x = r.x + sbo[c0    ] + sBd[c0    ][e];
            o.y = r.y + sbo[c0 + 1] + sBd[c0 + 1][e];
            *(float2*)(out + (size_t)eg * EDIM + c0) = o;   // 8B-aligned (c0 in {0,2})
        }
    }
}

extern "C" void kernel_launch(void* const* d_in, const int* in_sizes, int n_in,
                              void* d_out, int out_size)
{
    const float* x    = (const float*)d_in[0];
    const void*  eidx = d_in[1];
    const float* Wdir = (const float*)d_in[2];
    const float* bdir = (const float*)d_in[3];
    const float* W1   = (const float*)d_in[4];
    const float* b1   = (const float*)d_in[5];
    const float* W2   = (const float*)d_in[6];
    const float* b2   = (const float*)d_in[7];
    const float* W3   = (const float*)d_in[8];
    const float* b3   = (const float*)d_in[9];
    float* out = (float*)d_out;

    int n_nodes = in_sizes[0] / LATENT;
    int n_edges = in_sizes[1] / 2;

    // 1) detect index dtype (int64 vs int32)
    reset_flag_kernel<<<1, 1>>>();
    probe_kernel<<<(n_edges + 255) / 256, 256>>>((const long long*)eidx, n_edges, n_nodes);

    // 2) per-node precompute
    node_pre_kernel<<<(n_nodes + 7) / 8, 256>>>(x, W1, Wdir, n_nodes);

    // 3) per-edge fused MLP
    int nblk = (n_edges + TILE_E - 1) / TILE_E;
    edge_kernel<<<nblk, 128>>>(x, eidx, Wdir, bdir, W1, b1, W2, b2, W3, b3,
                               out, n_edges, n_nodes);
}

// round 7
// speedup vs baseline: 1.2555x; 1.2555x over previous
#include <cuda_runtime.h>
#include <stdint.h>

#define LATENT 64
#define HID    32
#define EDIM   4
#define N_NODES_MAX 100000
#define TILE_E 128
#define SD_STRIDE 68   // 64 + 4 pad (272B rows, 16B aligned, bank-spread)
#define SH_STRIDE 36   // 32 + 4 pad (144B rows)

// Scratch (allocation-free rule: static __device__ arrays)
__device__ float g_P1[N_NODES_MAX * HID];    // x @ 0.5*(W1_min + W1_max)
__device__ float g_PD[N_NODES_MAX * EDIM];   // x @ 0.5*(Wd_min + Wd_max)
__device__ int   g_flag;                     // 0 => edge_index is int64, 1 => int32

// ---------- packed f32x2 helpers ----------
__device__ __forceinline__ void ffma2(unsigned long long &acc,
                                      unsigned long long a,
                                      unsigned long long b) {
    asm("fma.rn.f32x2 %0, %1, %2, %0;" : "+l"(acc) : "l"(a), "l"(b));
}
__device__ __forceinline__ float2 unpack2(unsigned long long v) {
    float2 f;
    asm("mov.b64 {%0, %1}, %2;" : "=f"(f.x), "=f"(f.y) : "l"(v));
    return f;
}

// ---------------- dtype detection ----------------
__global__ void reset_flag_kernel() { g_flag = 0; }

__global__ __launch_bounds__(256) void probe_kernel(
    const long long* __restrict__ e, int n_probe, int n_nodes)
{
    int i = blockIdx.x * 256 + threadIdx.x;
    if (i >= n_probe) return;
    long long v = __ldg(&e[i]);
    if (v < 0 || v >= (long long)n_nodes) atomicOr(&g_flag, 1);
}

// ---------------- Kernel A: per-node precompute ----------------
__global__ __launch_bounds__(256) void node_pre_kernel(
    const float* __restrict__ x,
    const float* __restrict__ W1,     // [128,32]
    const float* __restrict__ Wdir,   // [128,4]
    int n_nodes)
{
    __shared__ float sWs1[LATENT][HID];
    __shared__ float sWsD[LATENT][EDIM];
    int t = threadIdx.x;
    for (int i = t; i < LATENT * HID; i += 256) {
        int j = i >> 5, k = i & 31;
        sWs1[j][k] = 0.5f * (W1[j * HID + k] + W1[(j + LATENT) * HID + k]);
    }
    for (int i = t; i < LATENT * EDIM; i += 256) {
        int j = i >> 2, c = i & 3;
        sWsD[j][c] = 0.5f * (Wdir[j * EDIM + c] + Wdir[(j + LATENT) * EDIM + c]);
    }
    __syncthreads();

    int warp = t >> 5, lane = t & 31;
    int node = blockIdx.x * 8 + warp;
    if (node >= n_nodes) return;

    const float4* xr = (const float4*)(x + (size_t)node * LATENT);
    float acc = 0.f, accd = 0.f;
    #pragma unroll
    for (int i = 0; i < 16; i++) {
        float4 v = xr[i];
        int j = i * 4;
        acc = fmaf(v.x, sWs1[j    ][lane], acc);
        acc = fmaf(v.y, sWs1[j + 1][lane], acc);
        acc = fmaf(v.z, sWs1[j + 2][lane], acc);
        acc = fmaf(v.w, sWs1[j + 3][lane], acc);
        if (lane < EDIM) {
            accd = fmaf(v.x, sWsD[j    ][lane], accd);
            accd = fmaf(v.y, sWsD[j + 1][lane], accd);
            accd = fmaf(v.z, sWsD[j + 2][lane], accd);
            accd = fmaf(v.w, sWsD[j + 3][lane], accd);
        }
    }
    g_P1[(size_t)node * HID + lane] = acc;
    if (lane < EDIM) g_PD[(size_t)node * EDIM + lane] = accd;
}

// ---------------- Edge kernel: SMEM layout ----------------
struct Smem {
    float sD  [TILE_E * SD_STRIDE];   // |xs-xt| edge-major      34816 B
    float sB1 [TILE_E * SH_STRIDE];   // base -> later H2        18432 B
    float sH  [TILE_E * SH_STRIDE];   // stage-1 activations     18432 B
    float sBd [TILE_E * EDIM];        // direct-path base         2048 B
    float sW1T[HID * SD_STRIDE];      // [k][j] diff weights      8704 B
    float sW2T[HID * SH_STRIDE];      // [k][j]                   4608 B
    float sW3I[8 * 16];               // interleaved W3            512 B
    float sWdI[16 * 16];              // interleaved Wdir diff    1024 B
    float sb1[HID]; float sb2[HID]; float sbo[EDIM];
    int   sSrc[TILE_E]; int sTgt[TILE_E];
};

__global__ __launch_bounds__(128) void edge_kernel(
    const float* __restrict__ x,
    const void*  __restrict__ eidx,
    const float* __restrict__ Wdir, const float* __restrict__ bdir,
    const float* __restrict__ W1,   const float* __restrict__ b1,
    const float* __restrict__ W2,   const float* __restrict__ b2,
    const float* __restrict__ W3,   const float* __restrict__ b3,
    float* __restrict__ out, int n_edges, int n_nodes)
{
    extern __shared__ char smem_raw[];
    Smem* S = (Smem*)smem_raw;
    int t  = threadIdx.x;
    int e0 = blockIdx.x * TILE_E;

    // ---- stage 0: edge indices (dual dtype + clamp) ----
    {
        int eg = e0 + t;
        if (eg >= n_edges) eg = n_edges - 1;
        int src, tgt;
        if (g_flag == 0) {
            src = (int)__ldg(&((const long long*)eidx)[eg]);
            tgt = (int)__ldg(&((const long long*)eidx)[(size_t)n_edges + eg]);
        } else {
            src = __ldg(&((const int*)eidx)[eg]);
            tgt = __ldg(&((const int*)eidx)[(size_t)n_edges + eg]);
        }
        S->sSrc[t] = min(max(src, 0), n_nodes - 1);
        S->sTgt[t] = min(max(tgt, 0), n_nodes - 1);
    }
    // ---- stage weights (transposed / interleaved) ----
    for (int idx = t; idx < HID * LATENT; idx += 128) {
        int k = idx & 31, j = idx >> 5;
        S->sW1T[k * SD_STRIDE + j] = 0.5f * (W1[(j + LATENT) * HID + k] - W1[j * HID + k]);
    }
    for (int idx = t; idx < HID * HID; idx += 128) {
        int k = idx & 31, j = idx >> 5;
        S->sW2T[k * SH_STRIDE + j] = W2[j * HID + k];
    }
    {   // W3 interleaved: block J holds (j,j+1) then (j+2,j+3) pairs per col
        int J = t >> 4, rem = t & 15, q = rem >> 3, c = (rem >> 1) & 3, r = rem & 1;
        int j = 4 * J + 2 * q + r;
        S->sW3I[t] = W3[j * EDIM + c];
    }
    for (int idx = t; idx < 256; idx += 128) {
        int J = idx >> 4, rem = idx & 15, q = rem >> 3, c = (rem >> 1) & 3, r = rem & 1;
        int j = 4 * J + 2 * q + r;
        S->sWdI[idx] = 0.5f * (Wdir[(j + LATENT) * EDIM + c] - Wdir[j * EDIM + c]);
    }
    if (t < HID)  { S->sb1[t] = b1[t]; S->sb2[t] = b2[t]; }
    if (t < EDIM) S->sbo[t] = b3[t] + bdir[t];
    __syncthreads();

    // ---- Phase A: coalesced gathers ----
    {   // x: 16 lanes per edge row (lane = one float4 chunk)
        int c = t & 15, el = t >> 4;
        #pragma unroll
        for (int p = 0; p < 16; p++) {
            int e = el + 8 * p;
            int src = S->sSrc[e], tgt = S->sTgt[e];
            float4 a = *(const float4*)(x + (size_t)src * LATENT + c * 4);
            float4 b = *(const float4*)(x + (size_t)tgt * LATENT + c * 4);
            float4 d;
            d.x = fabsf(a.x - b.x); d.y = fabsf(a.y - b.y);
            d.z = fabsf(a.z - b.z); d.w = fabsf(a.w - b.w);
            *(float4*)&S->sD[e * SD_STRIDE + c * 4] = d;
        }
    }
    {   // P1: 8 lanes per row
        int c = t & 7, el = t >> 3;
        #pragma unroll
        for (int p = 0; p < 8; p++) {
            int e = el + 16 * p;
            int src = S->sSrc[e], tgt = S->sTgt[e];
            float4 a = *(const float4*)(g_P1 + (size_t)src * HID + c * 4);
            float4 b = *(const float4*)(g_P1 + (size_t)tgt * HID + c * 4);
            float4 s; s.x = a.x + b.x; s.y = a.y + b.y; s.z = a.z + b.z; s.w = a.w + b.w;
            *(float4*)&S->sB1[e * SH_STRIDE + c * 4] = s;
        }
    }
    {   // PD: one edge per thread
        int src = S->sSrc[t], tgt = S->sTgt[t];
        float4 a = *(const float4*)(g_PD + (size_t)src * EDIM);
        float4 b = *(const float4*)(g_PD + (size_t)tgt * EDIM);
        float4 s; s.x = a.x + b.x; s.y = a.y + b.y; s.z = a.z + b.z; s.w = a.w + b.w;
        *(float4*)&S->sBd[t * EDIM] = s;
    }
    __syncthreads();

    // GEMM thread mapping: mg = edge group (edges mg+16m), ng = col group (4 cols)
    int mg = t & 15, ng = t >> 4;
    int kc = ng * 4;
    float hk[8][4];   // keep h1 for residual in Phase C

    // ---- Phase B: h1 = relu(sD @ W1diff + base + b1) ----
    {
        unsigned long long acc[8][4];
        #pragma unroll
        for (int m = 0; m < 8; m++) { acc[m][0]=0; acc[m][1]=0; acc[m][2]=0; acc[m][3]=0; }

        #pragma unroll 1
        for (int j4 = 0; j4 < LATENT; j4 += 4) {
            ulonglong2 w0 = *(const ulonglong2*)&S->sW1T[(kc + 0) * SD_STRIDE + j4];
            ulonglong2 w1 = *(const ulonglong2*)&S->sW1T[(kc + 1) * SD_STRIDE + j4];
            ulonglong2 w2 = *(const ulonglong2*)&S->sW1T[(kc + 2) * SD_STRIDE + j4];
            ulonglong2 w3 = *(const ulonglong2*)&S->sW1T[(kc + 3) * SD_STRIDE + j4];
            #pragma unroll
            for (int m = 0; m < 8; m++) {
                int e = mg + 16 * m;
                ulonglong2 d = *(const ulonglong2*)&S->sD[e * SD_STRIDE + j4];
                ffma2(acc[m][0], d.x, w0.x); ffma2(acc[m][0], d.y, w0.y);
                ffma2(acc[m][1], d.x, w1.x); ffma2(acc[m][1], d.y, w1.y);
                ffma2(acc[m][2], d.x, w2.x); ffma2(acc[m][2], d.y, w2.y);
                ffma2(acc[m][3], d.x, w3.x); ffma2(acc[m][3], d.y, w3.y);
            }
        }
        float bb0 = S->sb1[kc], bb1 = S->sb1[kc+1], bb2 = S->sb1[kc+2], bb3 = S->sb1[kc+3];
        #pragma unroll
        for (int m = 0; m < 8; m++) {
            int e = mg + 16 * m;
            float4 base = *(const float4*)&S->sB1[e * SH_STRIDE + kc];
            float2 r0 = unpack2(acc[m][0]);
            float2 r1 = unpack2(acc[m][1]);
            float2 r2 = unpack2(acc[m][2]);
            float2 r3 = unpack2(acc[m][3]);
            float4 hv;
            hv.x = fmaxf(r0.x + r0.y + base.x + bb0, 0.f);
            hv.y = fmaxf(r1.x + r1.y + base.y + bb1, 0.f);
            hv.z = fmaxf(r2.x + r2.y + base.z + bb2, 0.f);
            hv.w = fmaxf(r3.x + r3.y + base.w + bb3, 0.f);
            hk[m][0] = hv.x; hk[m][1] = hv.y; hk[m][2] = hv.z; hk[m][3] = hv.w;
            *(float4*)&S->sH[e * SH_STRIDE + kc] = hv;
        }
    }
    __syncthreads();

    // ---- Phase C: H2 = relu(h1 @ W2 + b2 + h1) -> sB1 (overwrites base) ----
    {
        unsigned long long acc[8][4];
        #pragma unroll
        for (int m = 0; m < 8; m++) { acc[m][0]=0; acc[m][1]=0; acc[m][2]=0; acc[m][3]=0; }

        #pragma unroll 1
        for (int j4 = 0; j4 < HID; j4 += 4) {
            ulonglong2 w0 = *(const ulonglong2*)&S->sW2T[(kc + 0) * SH_STRIDE + j4];
            ulonglong2 w1 = *(const ulonglong2*)&S->sW2T[(kc + 1) * SH_STRIDE + j4];
            ulonglong2 w2 = *(const ulonglong2*)&S->sW2T[(kc + 2) * SH_STRIDE + j4];
            ulonglong2 w3 = *(const ulonglong2*)&S->sW2T[(kc + 3) * SH_STRIDE + j4];
            #pragma unroll
            for (int m = 0; m < 8; m++) {
                int e = mg + 16 * m;
                ulonglong2 h = *(const ulonglong2*)&S->sH[e * SH_STRIDE + j4];
                ffma2(acc[m][0], h.x, w0.x); ffma2(acc[m][0], h.y, w0.y);
                ffma2(acc[m][1], h.x, w1.x); ffma2(acc[m][1], h.y, w1.y);
                ffma2(acc[m][2], h.x, w2.x); ffma2(acc[m][2], h.y, w2.y);
                ffma2(acc[m][3], h.x, w3.x); ffma2(acc[m][3], h.y, w3.y);
            }
        }
        float bb0 = S->sb2[kc], bb1 = S->sb2[kc+1], bb2 = S->sb2[kc+2], bb3 = S->sb2[kc+3];
        #pragma unroll
        for (int m = 0; m < 8; m++) {
            int e = mg + 16 * m;
            float2 r0 = unpack2(acc[m][0]);
            float2 r1 = unpack2(acc[m][1]);
            float2 r2 = unpack2(acc[m][2]);
            float2 r3 = unpack2(acc[m][3]);
            float4 hv;
            hv.x = fmaxf(r0.x + r0.y + hk[m][0] + bb0, 0.f);
            hv.y = fmaxf(r1.x + r1.y + hk[m][1] + bb1, 0.f);
            hv.z = fmaxf(r2.x + r2.y + hk[m][2] + bb2, 0.f);
            hv.w = fmaxf(r3.x + r3.y + hk[m][3] + bb3, 0.f);
            *(float4*)&S->sB1[e * SH_STRIDE + kc] = hv;
        }
    }
    __syncthreads();

    // ---- Phase D: one thread per edge; out = H2@W3 + D@WdD + biases + Bd ----
    {
        int e = t;
        unsigned long long acc[4] = {0ull, 0ull, 0ull, 0ull};
        #pragma unroll
        for (int J = 0; J < 8; J++) {
            ulonglong2 h  = *(const ulonglong2*)&S->sB1[e * SH_STRIDE + 4 * J];
            ulonglong2 wa = *(const ulonglong2*)&S->sW3I[J * 16];
            ulonglong2 wb = *(const ulonglong2*)&S->sW3I[J * 16 + 4];
            ulonglong2 wc = *(const ulonglong2*)&S->sW3I[J * 16 + 8];
            ulonglong2 wd = *(const ulonglong2*)&S->sW3I[J * 16 + 12];
            ffma2(acc[0], h.x, wa.x); ffma2(acc[1], h.x, wa.y);
            ffma2(acc[2], h.x, wb.x); ffma2(acc[3], h.x, wb.y);
            ffma2(acc[0], h.y, wc.x); ffma2(acc[1], h.y, wc.y);
            ffma2(acc[2], h.y, wd.x); ffma2(acc[3], h.y, wd.y);
        }
        #pragma unroll
        for (int J = 0; J < 16; J++) {
            ulonglong2 d  = *(const ulonglong2*)&S->sD[e * SD_STRIDE + 4 * J];
            ulonglong2 wa = *(const ulonglong2*)&S->sWdI[J * 16];
            ulonglong2 wb = *(const ulonglong2*)&S->sWdI[J * 16 + 4];
            ulonglong2 wc = *(const ulonglong2*)&S->sWdI[J * 16 + 8];
            ulonglong2 wd = *(const ulonglong2*)&S->sWdI[J * 16 + 12];
            ffma2(acc[0], d.x, wa.x); ffma2(acc[1], d.x, wa.y);
            ffma2(acc[2], d.x, wb.x); ffma2(acc[3], d.x, wb.y);
            ffma2(acc[0], d.y, wc.x); ffma2(acc[1], d.y, wc.y);
            ffma2(acc[2], d.y, wd.x); ffma2(acc[3], d.y, wd.y);
        }
        float4 bd = *(const float4*)&S->sBd[e * EDIM];
        float2 r0 = unpack2(acc[0]);
        float2 r1 = unpack2(acc[1]);
        float2 r2 = unpack2(acc[2]);
        float2 r3 = unpack2(acc[3]);
        float4 o;
        o.x = r0.x + r0.y + S->sbo[0] + bd.x;
        o.y = r1.x + r1.y + S->sbo[1] + bd.y;
        o.z = r2.x + r2.y + S->sbo[2] + bd.z;
        o.w = r3.x + r3.y + S->sbo[3] + bd.w;
        int eg = e0 + e;
        if (eg < n_edges) *(float4*)(out + (size_t)eg * EDIM) = o;
    }
}

extern "C" void kernel_launch(void* const* d_in, const int* in_sizes, int n_in,
                              void* d_out, int out_size)
{
    const float* x    = (const float*)d_in[0];
    const void*  eidx = d_in[1];
    const float* Wdir = (const float*)d_in[2];
    const float* bdir = (const float*)d_in[3];
    const float* W1   = (const float*)d_in[4];
    const float* b1   = (const float*)d_in[5];
    const float* W2   = (const float*)d_in[6];
    const float* b2   = (const float*)d_in[7];
    const float* W3   = (const float*)d_in[8];
    const float* b3   = (const float*)d_in[9];
    float* out = (float*)d_out;

    int n_nodes = in_sizes[0] / LATENT;
    int n_edges = in_sizes[1] / 2;

    reset_flag_kernel<<<1, 1>>>();
    probe_kernel<<<(n_edges + 255) / 256, 256>>>((const long long*)eidx, n_edges, n_nodes);

    node_pre_kernel<<<(n_nodes + 7) / 8, 256>>>(x, W1, Wdir, n_nodes);

    cudaFuncSetAttribute(edge_kernel, cudaFuncAttributeMaxDynamicSharedMemorySize,
                         (int)sizeof(Smem));
    int nblk = (n_edges + TILE_E - 1) / TILE_E;
    edge_kernel<<<nblk, 128, sizeof(Smem)>>>(x, eidx, Wdir, bdir, W1, b1, W2, b2,
                                             W3, b3, out, n_edges, n_nodes);
}

// round 8
// speedup vs baseline: 1.6124x; 1.2843x over previous
#include <cuda_runtime.h>
#include <stdint.h>

#define LATENT 64
#define HID    32
#define EDIM   4
#define N_NODES_MAX 100000
#define TILE_E 128
#define SD_STRIDE 68   // 64 + 4 pad
#define SH_STRIDE 36   // 32 + 4 pad

__device__ float g_P1[N_NODES_MAX * HID];
__device__ float g_PD[N_NODES_MAX * EDIM];
__device__ int   g_flag;   // 0 => edge_index int64, 1 => int32

__device__ __forceinline__ void ffma2(unsigned long long &acc,
                                      unsigned long long a,
                                      unsigned long long b) {
    asm("fma.rn.f32x2 %0, %1, %2, %0;" : "+l"(acc) : "l"(a), "l"(b));
}
__device__ __forceinline__ float2 unpack2(unsigned long long v) {
    float2 f;
    asm("mov.b64 {%0, %1}, %2;" : "=f"(f.x), "=f"(f.y) : "l"(v));
    return f;
}

// ---------------- dtype detection ----------------
__global__ void reset_flag_kernel() { g_flag = 0; }

__global__ __launch_bounds__(256) void probe_kernel(
    const long long* __restrict__ e, int n_probe, int n_nodes)
{
    int i = blockIdx.x * 256 + threadIdx.x;
    if (i >= n_probe) return;
    long long v = __ldg(&e[i]);
    if (v < 0 || v >= (long long)n_nodes) atomicOr(&g_flag, 1);
}

// ---------------- Kernel A: per-node precompute ----------------
__global__ __launch_bounds__(256) void node_pre_kernel(
    const float* __restrict__ x,
    const float* __restrict__ W1,
    const float* __restrict__ Wdir,
    int n_nodes)
{
    __shared__ float sWs1[LATENT][HID];
    __shared__ float sWsD[LATENT][EDIM];
    int t = threadIdx.x;
    for (int i = t; i < LATENT * HID; i += 256) {
        int j = i >> 5, k = i & 31;
        sWs1[j][k] = 0.5f * (W1[j * HID + k] + W1[(j + LATENT) * HID + k]);
    }
    for (int i = t; i < LATENT * EDIM; i += 256) {
        int j = i >> 2, c = i & 3;
        sWsD[j][c] = 0.5f * (Wdir[j * EDIM + c] + Wdir[(j + LATENT) * EDIM + c]);
    }
    __syncthreads();

    int warp = t >> 5, lane = t & 31;
    int node = blockIdx.x * 8 + warp;
    if (node >= n_nodes) return;

    const float4* xr = (const float4*)(x + (size_t)node * LATENT);
    float acc0 = 0.f, acc1 = 0.f, accd0 = 0.f, accd1 = 0.f;
    #pragma unroll
    for (int i = 0; i < 16; i += 2) {
        float4 v0 = xr[i], v1 = xr[i + 1];
        int j = i * 4;
        acc0 = fmaf(v0.x, sWs1[j    ][lane], acc0);
        acc0 = fmaf(v0.y, sWs1[j + 1][lane], acc0);
        acc0 = fmaf(v0.z, sWs1[j + 2][lane], acc0);
        acc0 = fmaf(v0.w, sWs1[j + 3][lane], acc0);
        acc1 = fmaf(v1.x, sWs1[j + 4][lane], acc1);
        acc1 = fmaf(v1.y, sWs1[j + 5][lane], acc1);
        acc1 = fmaf(v1.z, sWs1[j + 6][lane], acc1);
        acc1 = fmaf(v1.w, sWs1[j + 7][lane], acc1);
        if (lane < EDIM) {
            accd0 = fmaf(v0.x, sWsD[j    ][lane], accd0);
            accd0 = fmaf(v0.y, sWsD[j + 1][lane], accd0);
            accd0 = fmaf(v0.z, sWsD[j + 2][lane], accd0);
            accd0 = fmaf(v0.w, sWsD[j + 3][lane], accd0);
            accd1 = fmaf(v1.x, sWsD[j + 4][lane], accd1);
            accd1 = fmaf(v1.y, sWsD[j + 5][lane], accd1);
            accd1 = fmaf(v1.z, sWsD[j + 6][lane], accd1);
            accd1 = fmaf(v1.w, sWsD[j + 7][lane], accd1);
        }
    }
    g_P1[(size_t)node * HID + lane] = acc0 + acc1;
    if (lane < EDIM) g_PD[(size_t)node * EDIM + lane] = accd0 + accd1;
}

// ---------------- Edge kernel ----------------
struct Smem {
    float sD  [TILE_E * SD_STRIDE];   // 34816 B  |xs-xt| edge-major
    float sB1 [TILE_E * SH_STRIDE];   // 18432 B  base -> later H2
    float sH  [TILE_E * SH_STRIDE];   // 18432 B  stage-1 activations
    float sBd [TILE_E * EDIM];        //  2048 B
    float sW1T[HID * SD_STRIDE];      //  8704 B  [k][j]
    float sW2T[HID * SH_STRIDE];      //  4608 B  [k][j]
    float sW3P[8 * 16];               //   512 B  pair-packed [J][c][q][r]
    float sWdP[16 * 16];              //  1024 B  pair-packed diff
    float sb1[HID]; float sb2[HID]; float sbo[EDIM];
    int   sSrc[TILE_E]; int sTgt[TILE_E];
};

__global__ __launch_bounds__(256, 2) void edge_kernel(
    const float* __restrict__ x,
    const void*  __restrict__ eidx,
    const float* __restrict__ Wdir, const float* __restrict__ bdir,
    const float* __restrict__ W1,   const float* __restrict__ b1,
    const float* __restrict__ W2,   const float* __restrict__ b2,
    const float* __restrict__ W3,   const float* __restrict__ b3,
    float* __restrict__ out, int n_edges, int n_nodes)
{
    extern __shared__ char smem_raw[];
    Smem* S = (Smem*)smem_raw;
    int t  = threadIdx.x;
    int e0 = blockIdx.x * TILE_E;

    // ---- stage 0: edge indices (dual dtype + clamp), threads 0..127 ----
    if (t < TILE_E) {
        int eg = e0 + t;
        if (eg >= n_edges) eg = n_edges - 1;
        int src, tgt;
        if (g_flag == 0) {
            src = (int)__ldg(&((const long long*)eidx)[eg]);
            tgt = (int)__ldg(&((const long long*)eidx)[(size_t)n_edges + eg]);
        } else {
            src = __ldg(&((const int*)eidx)[eg]);
            tgt = __ldg(&((const int*)eidx)[(size_t)n_edges + eg]);
        }
        S->sSrc[t] = min(max(src, 0), n_nodes - 1);
        S->sTgt[t] = min(max(tgt, 0), n_nodes - 1);
    }
    // ---- stage weights ----
    for (int idx = t; idx < HID * LATENT; idx += 256) {
        int k = idx & 31, j = idx >> 5;
        S->sW1T[k * SD_STRIDE + j] = 0.5f * (W1[(j + LATENT) * HID + k] - W1[j * HID + k]);
    }
    for (int idx = t; idx < HID * HID; idx += 256) {
        int k = idx & 31, j = idx >> 5;
        S->sW2T[k * SH_STRIDE + j] = W2[j * HID + k];
    }
    if (t < 128) {   // sW3P: idx = J*16 + c*4 + q*2 + r  -> W3[(4J+2q+r)][c]
        int J = t >> 4, c = (t >> 2) & 3, q = (t >> 1) & 1, r = t & 1;
        S->sW3P[t] = W3[(4 * J + 2 * q + r) * EDIM + c];
    }
    if (t < 256) {   // sWdP: 16 J-blocks
        int J = t >> 4, c = (t >> 2) & 3, q = (t >> 1) & 1, r = t & 1;
        int j = 4 * J + 2 * q + r;
        S->sWdP[t] = 0.5f * (Wdir[(j + LATENT) * EDIM + c] - Wdir[j * EDIM + c]);
    }
    if (t < HID)  { S->sb1[t] = b1[t]; S->sb2[t] = b2[t]; }
    if (t < EDIM) S->sbo[t] = b3[t] + bdir[t];
    __syncthreads();

    // ---- Phase A: coalesced gathers (256 threads) ----
    {   // x: 16 lanes per edge row
        int c = t & 15, el = t >> 4;          // el in [0,16)
        #pragma unroll
        for (int p = 0; p < 8; p++) {
            int e = el + 16 * p;
            int src = S->sSrc[e], tgt = S->sTgt[e];
            float4 a = *(const float4*)(x + (size_t)src * LATENT + c * 4);
            float4 b = *(const float4*)(x + (size_t)tgt * LATENT + c * 4);
            float4 d;
            d.x = fabsf(a.x - b.x); d.y = fabsf(a.y - b.y);
            d.z = fabsf(a.z - b.z); d.w = fabsf(a.w - b.w);
            *(float4*)&S->sD[e * SD_STRIDE + c * 4] = d;
        }
    }
    {   // P1: 8 lanes per row
        int c = t & 7, el = t >> 3;           // el in [0,32)
        #pragma unroll
        for (int p = 0; p < 4; p++) {
            int e = el + 32 * p;
            int src = S->sSrc[e], tgt = S->sTgt[e];
            float4 a = *(const float4*)(g_P1 + (size_t)src * HID + c * 4);
            float4 b = *(const float4*)(g_P1 + (size_t)tgt * HID + c * 4);
            float4 s; s.x = a.x + b.x; s.y = a.y + b.y; s.z = a.z + b.z; s.w = a.w + b.w;
            *(float4*)&S->sB1[e * SH_STRIDE + c * 4] = s;
        }
    }
    if (t < TILE_E) {   // PD
        int src = S->sSrc[t], tgt = S->sTgt[t];
        float4 a = *(const float4*)(g_PD + (size_t)src * EDIM);
        float4 b = *(const float4*)(g_PD + (size_t)tgt * EDIM);
        float4 s; s.x = a.x + b.x; s.y = a.y + b.y; s.z = a.z + b.z; s.w = a.w + b.w;
        *(float4*)&S->sBd[t * EDIM] = s;
    }
    __syncthreads();

    // GEMM mapping: mg = lane (32 edge groups), ng = warp (8 col groups)
    int mg = t & 31, ng = t >> 5;
    int kc = ng * 4;
    float hk[4][4];

    // ---- Phase B: h1 = relu(sD @ W1diff + base + b1) ----
    {
        unsigned long long acc[4][4];
        #pragma unroll
        for (int m = 0; m < 4; m++) { acc[m][0]=0; acc[m][1]=0; acc[m][2]=0; acc[m][3]=0; }

        #pragma unroll 1
        for (int j4 = 0; j4 < LATENT; j4 += 4) {
            ulonglong2 w0 = *(const ulonglong2*)&S->sW1T[(kc + 0) * SD_STRIDE + j4];
            ulonglong2 w1 = *(const ulonglong2*)&S->sW1T[(kc + 1) * SD_STRIDE + j4];
            ulonglong2 w2 = *(const ulonglong2*)&S->sW1T[(kc + 2) * SD_STRIDE + j4];
            ulonglong2 w3 = *(const ulonglong2*)&S->sW1T[(kc + 3) * SD_STRIDE + j4];
            #pragma unroll
            for (int m = 0; m < 4; m++) {
                int e = mg + 32 * m;
                ulonglong2 d = *(const ulonglong2*)&S->sD[e * SD_STRIDE + j4];
                ffma2(acc[m][0], d.x, w0.x); ffma2(acc[m][0], d.y, w0.y);
                ffma2(acc[m][1], d.x, w1.x); ffma2(acc[m][1], d.y, w1.y);
                ffma2(acc[m][2], d.x, w2.x); ffma2(acc[m][2], d.y, w2.y);
                ffma2(acc[m][3], d.x, w3.x); ffma2(acc[m][3], d.y, w3.y);
            }
        }
        float bb0 = S->sb1[kc], bb1 = S->sb1[kc+1], bb2 = S->sb1[kc+2], bb3 = S->sb1[kc+3];
        #pragma unroll
        for (int m = 0; m < 4; m++) {
            int e = mg + 32 * m;
            float4 base = *(const float4*)&S->sB1[e * SH_STRIDE + kc];
            float2 r0 = unpack2(acc[m][0]);
            float2 r1 = unpack2(acc[m][1]);
            float2 r2 = unpack2(acc[m][2]);
            float2 r3 = unpack2(acc[m][3]);
            float4 hv;
            hv.x = fmaxf(r0.x + r0.y + base.x + bb0, 0.f);
            hv.y = fmaxf(r1.x + r1.y + base.y + bb1, 0.f);
            hv.z = fmaxf(r2.x + r2.y + base.z + bb2, 0.f);
            hv.w = fmaxf(r3.x + r3.y + base.w + bb3, 0.f);
            hk[m][0] = hv.x; hk[m][1] = hv.y; hk[m][2] = hv.z; hk[m][3] = hv.w;
            *(float4*)&S->sH[e * SH_STRIDE + kc] = hv;
        }
    }
    __syncthreads();

    // ---- Phase C: H2 = relu(h1 @ W2 + b2 + h1) -> sB1 ----
    {
        unsigned long long acc[4][4];
        #pragma unroll
        for (int m = 0; m < 4; m++) { acc[m][0]=0; acc[m][1]=0; acc[m][2]=0; acc[m][3]=0; }

        #pragma unroll 1
        for (int j4 = 0; j4 < HID; j4 += 4) {
            ulonglong2 w0 = *(const ulonglong2*)&S->sW2T[(kc + 0) * SH_STRIDE + j4];
            ulonglong2 w1 = *(const ulonglong2*)&S->sW2T[(kc + 1) * SH_STRIDE + j4];
            ulonglong2 w2 = *(const ulonglong2*)&S->sW2T[(kc + 2) * SH_STRIDE + j4];
            ulonglong2 w3 = *(const ulonglong2*)&S->sW2T[(kc + 3) * SH_STRIDE + j4];
            #pragma unroll
            for (int m = 0; m < 4; m++) {
                int e = mg + 32 * m;
                ulonglong2 h = *(const ulonglong2*)&S->sH[e * SH_STRIDE + j4];
                ffma2(acc[m][0], h.x, w0.x); ffma2(acc[m][0], h.y, w0.y);
                ffma2(acc[m][1], h.x, w1.x); ffma2(acc[m][1], h.y, w1.y);
                ffma2(acc[m][2], h.x, w2.x); ffma2(acc[m][2], h.y, w2.y);
                ffma2(acc[m][3], h.x, w3.x); ffma2(acc[m][3], h.y, w3.y);
            }
        }
        float bb0 = S->sb2[kc], bb1 = S->sb2[kc+1], bb2 = S->sb2[kc+2], bb3 = S->sb2[kc+3];
        #pragma unroll
        for (int m = 0; m < 4; m++) {
            int e = mg + 32 * m;
            float2 r0 = unpack2(acc[m][0]);
            float2 r1 = unpack2(acc[m][1]);
            float2 r2 = unpack2(acc[m][2]);
            float2 r3 = unpack2(acc[m][3]);
            float4 hv;
            hv.x = fmaxf(r0.x + r0.y + hk[m][0] + bb0, 0.f);
            hv.y = fmaxf(r1.x + r1.y + hk[m][1] + bb1, 0.f);
            hv.z = fmaxf(r2.x + r2.y + hk[m][2] + bb2, 0.f);
            hv.w = fmaxf(r3.x + r3.y + hk[m][3] + bb3, 0.f);
            *(float4*)&S->sB1[e * SH_STRIDE + kc] = hv;
        }
    }
    __syncthreads();

    // ---- Phase D: 2 threads per edge, 2 cols each ----
    {
        int e  = t >> 1;
        int c0 = (t & 1) * 2;
        unsigned long long acc[2] = {0ull, 0ull};
        #pragma unroll
        for (int J = 0; J < 8; J++) {
            ulonglong2 h  = *(const ulonglong2*)&S->sB1[e * SH_STRIDE + 4 * J];
            ulonglong2 wA = *(const ulonglong2*)&S->sW3P[J * 16 + c0 * 4];
            ulonglong2 wB = *(const ulonglong2*)&S->sW3P[J * 16 + (c0 + 1) * 4];
            ffma2(acc[0], h.x, wA.x); ffma2(acc[0], h.y, wA.y);
            ffma2(acc[1], h.x, wB.x); ffma2(acc[1], h.y, wB.y);
        }
        #pragma unroll
        for (int J = 0; J < 16; J++) {
            ulonglong2 d  = *(const ulonglong2*)&S->sD[e * SD_STRIDE + 4 * J];
            ulonglong2 wA = *(const ulonglong2*)&S->sWdP[J * 16 + c0 * 4];
            ulonglong2 wB = *(const ulonglong2*)&S->sWdP[J * 16 + (c0 + 1) * 4];
            ffma2(acc[0], d.x, wA.x); ffma2(acc[0], d.y, wA.y);
            ffma2(acc[1], d.x, wB.x); ffma2(acc[1], d.y, wB.y);
        }
        float2 r0 = unpack2(acc[0]);
        float2 r1 = unpack2(acc[1]);
        int eg = e0 + e;
        if (eg < n_edges) {
            float2 o;
            o.x = r0.x + r0.y + S->sbo[c0    ] + S->sBd[e * EDIM + c0];
            o.y = r1.x + r1.y + S->sbo[c0 + 1] + S->sBd[e * EDIM + c0 + 1];
            *(float2*)(out + (size_t)eg * EDIM + c0) = o;
        }
    }
}

extern "C" void kernel_launch(void* const* d_in, const int* in_sizes, int n_in,
                              void* d_out, int out_size)
{
    const float* x    = (const float*)d_in[0];
    const void*  eidx = d_in[1];
    const float* Wdir = (const float*)d_in[2];
    const float* bdir = (const float*)d_in[3];
    const float* W1   = (const float*)d_in[4];
    const float* b1   = (const float*)d_in[5];
    const float* W2   = (const float*)d_in[6];
    const float* b2   = (const float*)d_in[7];
    const float* W3   = (const float*)d_in[8];
    const float* b3   = (const float*)d_in[9];
    float* out = (float*)d_out;

    int n_nodes = in_sizes[0] / LATENT;
    int n_edges = in_sizes[1] / 2;

    reset_flag_kernel<<<1, 1>>>();
    probe_kernel<<<(n_edges + 255) / 256, 256>>>((const long long*)eidx, n_edges, n_nodes);

    node_pre_kernel<<<(n_nodes + 7) / 8, 256>>>(x, W1, Wdir, n_nodes);

    cudaFuncSetAttribute(edge_kernel, cudaFuncAttributeMaxDynamicSharedMemorySize,
                         (int)sizeof(Smem));
    int nblk = (n_edges + TILE_E - 1) / TILE_E;
    edge_kernel<<<nblk, 256, sizeof(Smem)>>>(x, eidx, Wdir, bdir, W1, b1, W2, b2,
                                             W3, b3, out, n_edges, n_nodes);
}

// round 9
// speedup vs baseline: 1.9388x; 1.2024x over previous
#include <cuda_runtime.h>
#include <stdint.h>

#define LATENT 64
#define HID    32
#define EDIM   4
#define N_NODES_MAX 100000
#define TILE_E 96
#define SD_STRIDE 68   // 64 + 4 pad
#define SH_STRIDE 36   // 32 + 4 pad

__device__ float g_P1[N_NODES_MAX * HID];
__device__ float g_PD[N_NODES_MAX * EDIM];
__device__ int   g_flag;   // 0 => edge_index int64, 1 => int32

__device__ __forceinline__ void ffma2(unsigned long long &acc,
                                      unsigned long long a,
                                      unsigned long long b) {
    asm("fma.rn.f32x2 %0, %1, %2, %0;" : "+l"(acc) : "l"(a), "l"(b));
}
__device__ __forceinline__ float2 unpack2(unsigned long long v) {
    float2 f;
    asm("mov.b64 {%0, %1}, %2;" : "=f"(f.x), "=f"(f.y) : "l"(v));
    return f;
}

// ---------------- dtype detection ----------------
__global__ void reset_flag_kernel() { g_flag = 0; }

// Sample the first n_probe int64 words (fits the buffer under both dtype
// interpretations). int32 storage => fused pairs exceed n_nodes virtually
// always; one warp-ballot atomic per warp max.
__global__ __launch_bounds__(256) void probe_kernel(
    const long long* __restrict__ e, int n_probe, int n_nodes)
{
    int i = blockIdx.x * 256 + threadIdx.x;
    bool bad = false;
    if (i < n_probe) {
        long long v = __ldg(&e[i]);
        bad = (v < 0 || v >= (long long)n_nodes);
    }
    unsigned m = __ballot_sync(0xFFFFFFFFu, bad);
    if (m && (threadIdx.x & 31) == 0) atomicOr(&g_flag, 1);
}

// ---------------- Kernel A: per-node precompute ----------------
__global__ __launch_bounds__(256) void node_pre_kernel(
    const float* __restrict__ x,
    const float* __restrict__ W1,
    const float* __restrict__ Wdir,
    int n_nodes)
{
    __shared__ float sWs1[LATENT][HID];
    __shared__ float sWsD[LATENT][EDIM];
    int t = threadIdx.x;
    for (int i = t; i < LATENT * HID; i += 256) {
        int j = i >> 5, k = i & 31;
        sWs1[j][k] = 0.5f * (W1[j * HID + k] + W1[(j + LATENT) * HID + k]);
    }
    for (int i = t; i < LATENT * EDIM; i += 256) {
        int j = i >> 2, c = i & 3;
        sWsD[j][c] = 0.5f * (Wdir[j * EDIM + c] + Wdir[(j + LATENT) * EDIM + c]);
    }
    __syncthreads();

    int warp = t >> 5, lane = t & 31;
    int node = blockIdx.x * 8 + warp;
    if (node >= n_nodes) return;

    const float4* xr = (const float4*)(x + (size_t)node * LATENT);
    float acc0 = 0.f, acc1 = 0.f, accd0 = 0.f, accd1 = 0.f;
    #pragma unroll
    for (int i = 0; i < 16; i += 2) {
        float4 v0 = xr[i], v1 = xr[i + 1];
        int j = i * 4;
        acc0 = fmaf(v0.x, sWs1[j    ][lane], acc0);
        acc0 = fmaf(v0.y, sWs1[j + 1][lane], acc0);
        acc0 = fmaf(v0.z, sWs1[j + 2][lane], acc0);
        acc0 = fmaf(v0.w, sWs1[j + 3][lane], acc0);
        acc1 = fmaf(v1.x, sWs1[j + 4][lane], acc1);
        acc1 = fmaf(v1.y, sWs1[j + 5][lane], acc1);
        acc1 = fmaf(v1.z, sWs1[j + 6][lane], acc1);
        acc1 = fmaf(v1.w, sWs1[j + 7][lane], acc1);
        if (lane < EDIM) {
            accd0 = fmaf(v0.x, sWsD[j    ][lane], accd0);
            accd0 = fmaf(v0.y, sWsD[j + 1][lane], accd0);
            accd0 = fmaf(v0.z, sWsD[j + 2][lane], accd0);
            accd0 = fmaf(v0.w, sWsD[j + 3][lane], accd0);
            accd1 = fmaf(v1.x, sWsD[j + 4][lane], accd1);
            accd1 = fmaf(v1.y, sWsD[j + 5][lane], accd1);
            accd1 = fmaf(v1.z, sWsD[j + 6][lane], accd1);
            accd1 = fmaf(v1.w, sWsD[j + 7][lane], accd1);
        }
    }
    g_P1[(size_t)node * HID + lane] = acc0 + acc1;
    if (lane < EDIM) g_PD[(size_t)node * EDIM + lane] = accd0 + accd1;
}

// ---------------- Edge kernel ----------------
struct Smem {
    float sD  [TILE_E * SD_STRIDE];   // 26112 B
    float sB1 [TILE_E * SH_STRIDE];   // 13824 B
    float sH  [TILE_E * SH_STRIDE];   // 13824 B
    float sBd [TILE_E * EDIM];        //  1536 B
    float sW1T[HID * SD_STRIDE];      //  8704 B
    float sW2T[HID * SH_STRIDE];      //  4608 B
    float sW3P[8 * 16];               //   512 B
    float sWdP[16 * 16];              //  1024 B
    float sb1[HID]; float sb2[HID]; float sbo[EDIM];
    int   sSrc[TILE_E]; int sTgt[TILE_E];
};   // ~70 KB -> 3 CTAs/SM

__global__ __launch_bounds__(256, 3) void edge_kernel(
    const float* __restrict__ x,
    const void*  __restrict__ eidx,
    const float* __restrict__ Wdir, const float* __restrict__ bdir,
    const float* __restrict__ W1,   const float* __restrict__ b1,
    const float* __restrict__ W2,   const float* __restrict__ b2,
    const float* __restrict__ W3,   const float* __restrict__ b3,
    float* __restrict__ out, int n_edges, int n_nodes)
{
    extern __shared__ char smem_raw[];
    Smem* S = (Smem*)smem_raw;
    int t  = threadIdx.x;
    int e0 = blockIdx.x * TILE_E;

    // ---- stage 0: edge indices ----
    if (t < TILE_E) {
        int eg = e0 + t;
        if (eg >= n_edges) eg = n_edges - 1;
        int src, tgt;
        if (g_flag == 0) {
            src = (int)__ldg(&((const long long*)eidx)[eg]);
            tgt = (int)__ldg(&((const long long*)eidx)[(size_t)n_edges + eg]);
        } else {
            src = __ldg(&((const int*)eidx)[eg]);
            tgt = __ldg(&((const int*)eidx)[(size_t)n_edges + eg]);
        }
        S->sSrc[t] = min(max(src, 0), n_nodes - 1);
        S->sTgt[t] = min(max(tgt, 0), n_nodes - 1);
    }
    // ---- stage weights ----
    for (int idx = t; idx < HID * LATENT; idx += 256) {
        int k = idx & 31, j = idx >> 5;
        S->sW1T[k * SD_STRIDE + j] = 0.5f * (W1[(j + LATENT) * HID + k] - W1[j * HID + k]);
    }
    for (int idx = t; idx < HID * HID; idx += 256) {
        int k = idx & 31, j = idx >> 5;
        S->sW2T[k * SH_STRIDE + j] = W2[j * HID + k];
    }
    if (t < 128) {
        int J = t >> 4, c = (t >> 2) & 3, q = (t >> 1) & 1, r = t & 1;
        S->sW3P[t] = W3[(4 * J + 2 * q + r) * EDIM + c];
    }
    {
        int J = t >> 4, c = (t >> 2) & 3, q = (t >> 1) & 1, r = t & 1;
        int j = 4 * J + 2 * q + r;
        S->sWdP[t] = 0.5f * (Wdir[(j + LATENT) * EDIM + c] - Wdir[j * EDIM + c]);
    }
    if (t < HID)  { S->sb1[t] = b1[t]; S->sb2[t] = b2[t]; }
    if (t < EDIM) S->sbo[t] = b3[t] + bdir[t];
    __syncthreads();

    // ---- Phase A: coalesced gathers ----
    {   // x: 16 lanes per edge row
        int c = t & 15, el = t >> 4;          // el in [0,16)
        #pragma unroll
        for (int p = 0; p < 6; p++) {
            int e = el + 16 * p;
            int src = S->sSrc[e], tgt = S->sTgt[e];
            float4 a = *(const float4*)(x + (size_t)src * LATENT + c * 4);
            float4 b = *(const float4*)(x + (size_t)tgt * LATENT + c * 4);
            float4 d;
            d.x = fabsf(a.x - b.x); d.y = fabsf(a.y - b.y);
            d.z = fabsf(a.z - b.z); d.w = fabsf(a.w - b.w);
            *(float4*)&S->sD[e * SD_STRIDE + c * 4] = d;
        }
    }
    {   // P1: 8 lanes per row
        int c = t & 7, el = t >> 3;           // el in [0,32)
        #pragma unroll
        for (int p = 0; p < 3; p++) {
            int e = el + 32 * p;
            int src = S->sSrc[e], tgt = S->sTgt[e];
            float4 a = *(const float4*)(g_P1 + (size_t)src * HID + c * 4);
            float4 b = *(const float4*)(g_P1 + (size_t)tgt * HID + c * 4);
            float4 s; s.x = a.x + b.x; s.y = a.y + b.y; s.z = a.z + b.z; s.w = a.w + b.w;
            *(float4*)&S->sB1[e * SH_STRIDE + c * 4] = s;
        }
    }
    if (t < TILE_E) {   // PD
        int src = S->sSrc[t], tgt = S->sTgt[t];
        float4 a = *(const float4*)(g_PD + (size_t)src * EDIM);
        float4 b = *(const float4*)(g_PD + (size_t)tgt * EDIM);
        float4 s; s.x = a.x + b.x; s.y = a.y + b.y; s.z = a.z + b.z; s.w = a.w + b.w;
        *(float4*)&S->sBd[t * EDIM] = s;
    }
    __syncthreads();

    // GEMM mapping: mg = lane (32 edge groups), ng = warp (8 col groups), M=3
    int mg = t & 31, ng = t >> 5;
    int kc = ng * 4;
    float hk[3][4];

    // ---- Phase B: h1 = relu(sD @ W1diff + base + b1) ----
    {
        unsigned long long acc[3][4];
        #pragma unroll
        for (int m = 0; m < 3; m++) { acc[m][0]=0; acc[m][1]=0; acc[m][2]=0; acc[m][3]=0; }

        #pragma unroll 1
        for (int j4 = 0; j4 < LATENT; j4 += 4) {
            ulonglong2 w0 = *(const ulonglong2*)&S->sW1T[(kc + 0) * SD_STRIDE + j4];
            ulonglong2 w1 = *(const ulonglong2*)&S->sW1T[(kc + 1) * SD_STRIDE + j4];
            ulonglong2 w2 = *(const ulonglong2*)&S->sW1T[(kc + 2) * SD_STRIDE + j4];
            ulonglong2 w3 = *(const ulonglong2*)&S->sW1T[(kc + 3) * SD_STRIDE + j4];
            #pragma unroll
            for (int m = 0; m < 3; m++) {
                int e = mg + 32 * m;
                ulonglong2 d = *(const ulonglong2*)&S->sD[e * SD_STRIDE + j4];
                ffma2(acc[m][0], d.x, w0.x); ffma2(acc[m][0], d.y, w0.y);
                ffma2(acc[m][1], d.x, w1.x); ffma2(acc[m][1], d.y, w1.y);
                ffma2(acc[m][2], d.x, w2.x); ffma2(acc[m][2], d.y, w2.y);
                ffma2(acc[m][3], d.x, w3.x); ffma2(acc[m][3], d.y, w3.y);
            }
        }
        float bb0 = S->sb1[kc], bb1 = S->sb1[kc+1], bb2 = S->sb1[kc+2], bb3 = S->sb1[kc+3];
        #pragma unroll
        for (int m = 0; m < 3; m++) {
            int e = mg + 32 * m;
            float4 base = *(const float4*)&S->sB1[e * SH_STRIDE + kc];
            float2 r0 = unpack2(acc[m][0]);
            float2 r1 = unpack2(acc[m][1]);
            float2 r2 = unpack2(acc[m][2]);
            float2 r3 = unpack2(acc[m][3]);
            float4 hv;
            hv.x = fmaxf(r0.x + r0.y + base.x + bb0, 0.f);
            hv.y = fmaxf(r1.x + r1.y + base.y + bb1, 0.f);
            hv.z = fmaxf(r2.x + r2.y + base.z + bb2, 0.f);
            hv.w = fmaxf(r3.x + r3.y + base.w + bb3, 0.f);
            hk[m][0] = hv.x; hk[m][1] = hv.y; hk[m][2] = hv.z; hk[m][3] = hv.w;
            *(float4*)&S->sH[e * SH_STRIDE + kc] = hv;
        }
    }
    __syncthreads();

    // ---- Phase C: H2 = relu(h1 @ W2 + b2 + h1) -> sB1 ----
    {
        unsigned long long acc[3][4];
        #pragma unroll
        for (int m = 0; m < 3; m++) { acc[m][0]=0; acc[m][1]=0; acc[m][2]=0; acc[m][3]=0; }

        #pragma unroll 1
        for (int j4 = 0; j4 < HID; j4 += 4) {
            ulonglong2 w0 = *(const ulonglong2*)&S->sW2T[(kc + 0) * SH_STRIDE + j4];
            ulonglong2 w1 = *(const ulonglong2*)&S->sW2T[(kc + 1) * SH_STRIDE + j4];
            ulonglong2 w2 = *(const ulonglong2*)&S->sW2T[(kc + 2) * SH_STRIDE + j4];
            ulonglong2 w3 = *(const ulonglong2*)&S->sW2T[(kc + 3) * SH_STRIDE + j4];
            #pragma unroll
            for (int m = 0; m < 3; m++) {
                int e = mg + 32 * m;
                ulonglong2 h = *(const ulonglong2*)&S->sH[e * SH_STRIDE + j4];
                ffma2(acc[m][0], h.x, w0.x); ffma2(acc[m][0], h.y, w0.y);
                ffma2(acc[m][1], h.x, w1.x); ffma2(acc[m][1], h.y, w1.y);
                ffma2(acc[m][2], h.x, w2.x); ffma2(acc[m][2], h.y, w2.y);
                ffma2(acc[m][3], h.x, w3.x); ffma2(acc[m][3], h.y, w3.y);
            }
        }
        float bb0 = S->sb2[kc], bb1 = S->sb2[kc+1], bb2 = S->sb2[kc+2], bb3 = S->sb2[kc+3];
        #pragma unroll
        for (int m = 0; m < 3; m++) {
            int e = mg + 32 * m;
            float2 r0 = unpack2(acc[m][0]);
            float2 r1 = unpack2(acc[m][1]);
            float2 r2 = unpack2(acc[m][2]);
            float2 r3 = unpack2(acc[m][3]);
            float4 hv;
            hv.x = fmaxf(r0.x + r0.y + hk[m][0] + bb0, 0.f);
            hv.y = fmaxf(r1.x + r1.y + hk[m][1] + bb1, 0.f);
            hv.z = fmaxf(r2.x + r2.y + hk[m][2] + bb2, 0.f);
            hv.w = fmaxf(r3.x + r3.y + hk[m][3] + bb3, 0.f);
            *(float4*)&S->sB1[e * SH_STRIDE + kc] = hv;
        }
    }
    __syncthreads();

    // ---- Phase D: 2 threads per edge, 2 cols each (threads 0..191) ----
    if (t < 2 * TILE_E) {
        int e  = t >> 1;
        int c0 = (t & 1) * 2;
        unsigned long long acc[2] = {0ull, 0ull};
        #pragma unroll
        for (int J = 0; J < 8; J++) {
            ulonglong2 h  = *(const ulonglong2*)&S->sB1[e * SH_STRIDE + 4 * J];
            ulonglong2 wA = *(const ulonglong2*)&S->sW3P[J * 16 + c0 * 4];
            ulonglong2 wB = *(const ulonglong2*)&S->sW3P[J * 16 + (c0 + 1) * 4];
            ffma2(acc[0], h.x, wA.x); ffma2(acc[0], h.y, wA.y);
            ffma2(acc[1], h.x, wB.x); ffma2(acc[1], h.y, wB.y);
        }
        #pragma unroll
        for (int J = 0; J < 16; J++) {
            ulonglong2 d  = *(const ulonglong2*)&S->sD[e * SD_STRIDE + 4 * J];
            ulonglong2 wA = *(const ulonglong2*)&S->sWdP[J * 16 + c0 * 4];
            ulonglong2 wB = *(const ulonglong2*)&S->sWdP[J * 16 + (c0 + 1) * 4];
            ffma2(acc[0], d.x, wA.x); ffma2(acc[0], d.y, wA.y);
            ffma2(acc[1], d.x, wB.x); ffma2(acc[1], d.y, wB.y);
        }
        float2 r0 = unpack2(acc[0]);
        float2 r1 = unpack2(acc[1]);
        int eg = e0 + e;
        if (eg < n_edges) {
            float2 o;
            o.x = r0.x + r0.y + S->sbo[c0    ] + S->sBd[e * EDIM + c0];
            o.y = r1.x + r1.y + S->sbo[c0 + 1] + S->sBd[e * EDIM + c0 + 1];
            *(float2*)(out + (size_t)eg * EDIM + c0) = o;
        }
    }
}

extern "C" void kernel_launch(void* const* d_in, const int* in_sizes, int n_in,
                              void* d_out, int out_size)
{
    const float* x    = (const float*)d_in[0];
    const void*  eidx = d_in[1];
    const float* Wdir = (const float*)d_in[2];
    const float* bdir = (const float*)d_in[3];
    const float* W1   = (const float*)d_in[4];
    const float* b1   = (const float*)d_in[5];
    const float* W2   = (const float*)d_in[6];
    const float* b2   = (const float*)d_in[7];
    const float* W3   = (const float*)d_in[8];
    const float* b3   = (const float*)d_in[9];
    float* out = (float*)d_out;

    int n_nodes = in_sizes[0] / LATENT;
    int n_edges = in_sizes[1] / 2;

    int n_probe = n_edges < 32768 ? n_edges : 32768;
    reset_flag_kernel<<<1, 1>>>();
    probe_kernel<<<(n_probe + 255) / 256, 256>>>((const long long*)eidx, n_probe, n_nodes);

    node_pre_kernel<<<(n_nodes + 7) / 8, 256>>>(x, W1, Wdir, n_nodes);

    cudaFuncSetAttribute(edge_kernel, cudaFuncAttributeMaxDynamicSharedMemorySize,
                         (int)sizeof(Smem));
    int nblk = (n_edges + TILE_E - 1) / TILE_E;
    edge_kernel<<<nblk, 256, sizeof(Smem)>>>(x, eidx, Wdir, bdir, W1, b1, W2, b2,
                                             W3, b3, out, n_edges, n_nodes);
}